// round 13
// baseline (speedup 1.0000x reference)
#include <cuda_runtime.h>
#include <cuda_fp16.h>
#include <cstdint>
#include <math.h>

#define D 128
#define NMAX 100352
#define EMAX 131072
#define NQMAX 128
#define QCAP 4096

// ---------------- static scratch (allocation-free rule) ----------------
__device__ float    g_Qc   [NQMAX * 512];       // query combined (+bias folded)
__device__ float    g_bcat [512];               // [b_left ; b_right]
__device__ float    g_Pnode[NMAX * 512];
__device__ float    g_L  [EMAX * 256];
__device__ float    g_logits[EMAX];
__device__ float    g_ex[EMAX];
__device__ float    g_attn[EMAX];
__device__ float    g_scoreE[EMAX];
__device__ unsigned g_segmax[NMAX];
__device__ float    g_denom[NMAX];
__device__ float    g_agg[NMAX * D];            // attention-weighted message sum (zeroed)
__device__ int      g_keep[EMAX];               // final per-edge keep flag (zeroed)
__device__ int      g_qcnt[NQMAX];              // per-query bucket counts (zeroed)
__device__ unsigned g_qkey [NQMAX * QCAP];      // per-query score keys
__device__ int      g_qedge[NQMAX * QCAP];      // per-query edge ids

// split fp16 operand buffers (hi/lo)
__device__ __align__(128) __half g_WnodeH[512 * 128], g_WnodeL[512 * 128];
__device__ __align__(128) __half g_WrelH [512 * 128], g_WrelL [512 * 128];
__device__ __align__(128) __half g_WqH   [512 * 256], g_WqL   [512 * 256];
__device__ __align__(128) __half g_WcH   [256 * 256], g_WcL   [256 * 256];
__device__ __align__(128) __half g_WsH   [128 * 128], g_WsL   [128 * 128];
__device__ __align__(128) __half g_QinH  [NQMAX * 256], g_QinL[NQMAX * 256];
__device__ __align__(128) __half g_NodeH [NMAX * 128], g_NodeL[NMAX * 128];
__device__ __align__(128) __half g_RelH  [EMAX * 128], g_RelL [EMAX * 128];
__device__ __align__(128) __half g_R1H   [EMAX * 256], g_R1L  [EMAX * 256];

__device__ __forceinline__ float leaky(float x) { return x > 0.f ? x : 0.01f * x; }
__device__ __forceinline__ unsigned f2mono(float f) {
    unsigned b = __float_as_uint(f);
    return (b & 0x80000000u) ? ~b : (b | 0x80000000u);
}
__device__ __forceinline__ float mono2f(unsigned u) {
    return (u & 0x80000000u) ? __uint_as_float(u & 0x7fffffffu) : __uint_as_float(~u);
}
__device__ __forceinline__ uint32_t smem_u32(const void* p) {
    uint32_t a;
    asm("{ .reg .u64 t; cvta.to.shared.u64 t, %1; cvt.u32.u64 %0, t; }" : "=r"(a) : "l"(p));
    return a;
}
__device__ __forceinline__ void split_h(float v, __half& h, __half& l) {
    h = __float2half_rn(v);
    l = __float2half_rn(v - __half2float(h));
}
__device__ __forceinline__ void ldsm4(uint32_t* r, uint32_t addr) {
    asm volatile("ldmatrix.sync.aligned.m8n8.x4.shared.b16 {%0,%1,%2,%3}, [%4];"
                 : "=r"(r[0]), "=r"(r[1]), "=r"(r[2]), "=r"(r[3]) : "r"(addr));
}
__device__ __forceinline__ void mma_f16(float* d, const uint32_t* a, const uint32_t* b) {
    asm volatile(
        "mma.sync.aligned.m16n8k16.row.col.f32.f16.f16.f32 "
        "{%0,%1,%2,%3}, {%4,%5,%6,%7}, {%8,%9}, {%0,%1,%2,%3};"
        : "+f"(d[0]), "+f"(d[1]), "+f"(d[2]), "+f"(d[3])
        : "r"(a[0]), "r"(a[1]), "r"(a[2]), "r"(a[3]), "r"(b[0]), "r"(b[1]));
}

// ================= fp16 3-pass split GEMM: C[M,N] = A[M,K] @ B[N,K]^T =================
// MODE 0: plain store   1: bias+leaky store   2: bias store
// MODE 3: assemble-fused epilogue (Prel GEMM): gathers Pnode/Qc, leaky, writes L + split R1
// MODE 4: logits-fused epilogue (center GEMM): partial dot with L, atomicAdd into g_logits
// MODE 5: A = fp32(Pn + Qc2) summed+split in-register (step GEMM); bias+leaky store
// BN: N-tile width (128 or 256). Wider BN halves A-operand re-reads for big-N GEMMs.
#define ROWH 40
#define TILE_H (128 * ROWH)
#define SMEMB(BN) (2 * (2 * TILE_H + 2 * (BN) * ROWH) * 2)
template <int MODE, int BN>
__global__ __launch_bounds__(256) void gemm_f16(const __half* __restrict__ Ah,
                                                const __half* __restrict__ Al,
                                                const __half* __restrict__ Bh,
                                                const __half* __restrict__ Bl,
                                                float* __restrict__ C,
                                                const float* __restrict__ bias,
                                                int M, int N, int K,
                                                const int* __restrict__ idx_i,
                                                const int* __restrict__ idx_j,
                                                const int* __restrict__ qidx,
                                                const float* __restrict__ Pn,
                                                const float* __restrict__ Qc2,
                                                float* __restrict__ outL,
                                                __half* __restrict__ outRH,
                                                __half* __restrict__ outRL,
                                                const float* __restrict__ Lbuf) {
    constexpr int BTILE_H = BN * ROWH;
    constexpr int STG = 2 * TILE_H + 2 * BTILE_H;   // halves per stage
    constexpr int NT = BN / 32;                     // n-tiles per warp
    extern __shared__ __align__(128) __half sm[];
    const int tid = threadIdx.x, lane = tid & 31, wid = tid >> 5;
    const int wm = wid & 1, wn = wid >> 1;
    const int bm = blockIdx.y * 128, bn = blockIdx.x * BN;
    const int rl = lane & 7, q = lane >> 3;

    float acc[4][NT][4];
#pragma unroll
    for (int mt = 0; mt < 4; mt++)
#pragma unroll
        for (int nt = 0; nt < NT; nt++)
#pragma unroll
            for (int r = 0; r < 4; r++) acc[mt][nt][r] = 0.f;

    auto load_stage = [&](int st, int kc) {
        if constexpr (MODE == 5) {
#pragma unroll
            for (int i = 0; i < 4; i++) {
                int ch = tid + i * 256;
                int t2 = ch >> 9, r = (ch >> 2) & 127, seg = ch & 3;
                const __half* src = (t2 == 0 ? Bh : Bl) + (size_t)(bn + r) * K + kc + seg * 8;
                uint32_t dst = smem_u32(sm + st * STG + 2 * TILE_H + t2 * BTILE_H + r * ROWH + seg * 8);
                asm volatile("cp.async.cg.shared.global [%0], [%1], 16, 16;"
                             :: "r"(dst), "l"(src));
            }
            asm volatile("cp.async.commit_group;" ::: "memory");
#pragma unroll
            for (int i = 0; i < 4; i++) {
                int s = tid + i * 256;
                int r = s >> 3, c4 = (s & 7) * 4;
                int gm = bm + r;
                float4 va = make_float4(0.f, 0.f, 0.f, 0.f), vb = va;
                if (gm < M) {
                    va = *(const float4*)(Pn + (size_t)gm * K + kc + c4);
                    vb = *(const float4*)(Qc2 + (size_t)gm * K + kc + c4);
                }
                float f0 = va.x + vb.x, f1 = va.y + vb.y, f2 = va.z + vb.z, f3 = va.w + vb.w;
                __half h0, h1, h2, h3, l0, l1, l2, l3;
                split_h(f0, h0, l0); split_h(f1, h1, l1);
                split_h(f2, h2, l2); split_h(f3, h3, l3);
                __half* ah = sm + st * STG + r * ROWH + c4;
                __half* al = sm + st * STG + TILE_H + r * ROWH + c4;
                *(__half2*)(ah) = __halves2half2(h0, h1);
                *(__half2*)(ah + 2) = __halves2half2(h2, h3);
                *(__half2*)(al) = __halves2half2(l0, l1);
                *(__half2*)(al + 2) = __halves2half2(l2, l3);
            }
        } else {
            // A: 2*128 rows, B: 2*BN rows; 4 x 16B segments per row
#pragma unroll
            for (int ch = tid; ch < 1024 + 8 * BN; ch += 256) {
                const __half* src;
                uint32_t dst;
                int sz = 16;
                if (ch < 1024) {
                    int tile = ch >> 9, r = (ch >> 2) & 127, seg = ch & 3;
                    int row = bm + r;
                    int rc = row < M ? row : 0;
                    sz = row < M ? 16 : 0;
                    src = (tile == 0 ? Ah : Al) + (size_t)rc * K + kc + seg * 8;
                    dst = smem_u32(sm + st * STG + tile * TILE_H + r * ROWH + seg * 8);
                } else {
                    int c2 = ch - 1024;
                    int tile = c2 / (BN * 4);
                    int r = (c2 >> 2) % BN;
                    int seg = c2 & 3;
                    src = (tile == 0 ? Bh : Bl) + (size_t)(bn + r) * K + kc + seg * 8;
                    dst = smem_u32(sm + st * STG + 2 * TILE_H + tile * BTILE_H + r * ROWH + seg * 8);
                }
                asm volatile("cp.async.cg.shared.global [%0], [%1], 16, %2;"
                             :: "r"(dst), "l"(src), "r"(sz));
            }
            asm volatile("cp.async.commit_group;" ::: "memory");
        }
    };

    const int nch = K >> 5;
    load_stage(0, 0);

    for (int c = 0; c < nch; c++) {
        if (c + 1 < nch) {
            load_stage((c + 1) & 1, (c + 1) << 5);
            asm volatile("cp.async.wait_group 1;" ::: "memory");
        } else {
            asm volatile("cp.async.wait_group 0;" ::: "memory");
        }
        __syncthreads();

        const __half* base = sm + (c & 1) * STG;
        uint32_t aAh = smem_u32(base);
        uint32_t aAl = smem_u32(base + TILE_H);
        uint32_t aBh = smem_u32(base + 2 * TILE_H);
        uint32_t aBl = smem_u32(base + 2 * TILE_H + BTILE_H);

#pragma unroll
        for (int ks = 0; ks < 2; ks++) {
            uint32_t ah[4][4], al[4][4];
#pragma unroll
            for (int mt = 0; mt < 4; mt++) {
                uint32_t off = ((wm * 64 + mt * 16 + (q & 1) * 8 + rl) * ROWH +
                                ks * 16 + (q >> 1) * 8) * 2;
                ldsm4(ah[mt], aAh + off);
                ldsm4(al[mt], aAl + off);
            }
#pragma unroll
            for (int p = 0; p < NT / 2; p++) {
                uint32_t bh2[2][2], bl2[2][2];
                uint32_t off = ((wn * (BN / 4) + p * 16 + (q >> 1) * 8 + rl) * ROWH +
                                ks * 16 + (q & 1) * 8) * 2;
                uint32_t t[4];
                ldsm4(t, aBh + off);
                bh2[0][0] = t[0]; bh2[0][1] = t[1];
                bh2[1][0] = t[2]; bh2[1][1] = t[3];
                ldsm4(t, aBl + off);
                bl2[0][0] = t[0]; bl2[0][1] = t[1];
                bl2[1][0] = t[2]; bl2[1][1] = t[3];
#pragma unroll
                for (int mt = 0; mt < 4; mt++)
#pragma unroll
                    for (int s = 0; s < 2; s++) {
                        mma_f16(acc[mt][2 * p + s], ah[mt], bh2[s]);
                        mma_f16(acc[mt][2 * p + s], ah[mt], bl2[s]);
                        mma_f16(acc[mt][2 * p + s], al[mt], bh2[s]);
                    }
            }
        }
        __syncthreads();
    }

    // ---- epilogues ----
    const int g = lane >> 2, t4 = lane & 3;

    if constexpr (MODE == 3) {
        int* si = (int*)sm;
        if (tid < 128) {
            int e = bm + tid;
            si[tid] = idx_i[e];
            si[128 + tid] = idx_j[e];
            si[256 + tid] = qidx[e];
        }
        __syncthreads();
#pragma unroll
        for (int mt = 0; mt < 4; mt++) {
            int rl0 = wm * 64 + mt * 16 + g;
            int i0 = si[rl0], j0 = si[128 + rl0], q0 = si[256 + rl0];
            int i1 = si[rl0 + 8], j1 = si[128 + rl0 + 8], q1 = si[256 + rl0 + 8];
            size_t e0 = (size_t)bm + rl0, e1 = e0 + 8;
#pragma unroll
            for (int nt = 0; nt < NT; nt++) {
                int col = bn + wn * (BN / 4) + nt * 8 + t4 * 2;
                bool left = col < 256;
                int b0 = left ? i0 : j0, b1 = left ? i1 : j1;
                float2 pn0 = *(const float2*)(Pn + (size_t)b0 * 512 + col);
                float2 qc0 = *(const float2*)(Qc2 + (size_t)q0 * 512 + col);
                float2 pn1 = *(const float2*)(Pn + (size_t)b1 * 512 + col);
                float2 qc1 = *(const float2*)(Qc2 + (size_t)q1 * 512 + col);
                float v0 = leaky(acc[mt][nt][0] + pn0.x + qc0.x);
                float v1 = leaky(acc[mt][nt][1] + pn0.y + qc0.y);
                float v2 = leaky(acc[mt][nt][2] + pn1.x + qc1.x);
                float v3 = leaky(acc[mt][nt][3] + pn1.y + qc1.y);
                if (left) {
                    *(float2*)(outL + e0 * 256 + col) = make_float2(v0, v1);
                    *(float2*)(outL + e1 * 256 + col) = make_float2(v2, v3);
                } else {
                    __half h0, l0, h1, l1, h2, l2, h3, l3;
                    split_h(v0, h0, l0); split_h(v1, h1, l1);
                    split_h(v2, h2, l2); split_h(v3, h3, l3);
                    size_t o0 = e0 * 256 + col - 256, o1 = e1 * 256 + col - 256;
                    *(__half2*)(outRH + o0) = __halves2half2(h0, h1);
                    *(__half2*)(outRL + o0) = __halves2half2(l0, l1);
                    *(__half2*)(outRH + o1) = __halves2half2(h2, h3);
                    *(__half2*)(outRL + o1) = __halves2half2(l2, l3);
                }
            }
        }
    } else if constexpr (MODE == 4) {
#pragma unroll
        for (int mt = 0; mt < 4; mt++) {
            int r0 = bm + wm * 64 + mt * 16 + g;
            float p0 = 0.f, p1 = 0.f;
#pragma unroll
            for (int nt = 0; nt < NT; nt++) {
                int col = bn + wn * (BN / 4) + nt * 8 + t4 * 2;
                float b0 = bias[col], b1 = bias[col + 1];
                float2 l0 = *(const float2*)(Lbuf + (size_t)r0 * 256 + col);
                float2 l1 = *(const float2*)(Lbuf + (size_t)(r0 + 8) * 256 + col);
                p0 = fmaf(l0.x, acc[mt][nt][0] + b0, p0);
                p0 = fmaf(l0.y, acc[mt][nt][1] + b1, p0);
                p1 = fmaf(l1.x, acc[mt][nt][2] + b0, p1);
                p1 = fmaf(l1.y, acc[mt][nt][3] + b1, p1);
            }
            p0 += __shfl_xor_sync(0xffffffffu, p0, 1);
            p0 += __shfl_xor_sync(0xffffffffu, p0, 2);
            p1 += __shfl_xor_sync(0xffffffffu, p1, 1);
            p1 += __shfl_xor_sync(0xffffffffu, p1, 2);
            if (t4 == 0) {
                atomicAdd(&g_logits[r0], p0);
                atomicAdd(&g_logits[r0 + 8], p1);
            }
        }
    } else {
#pragma unroll
        for (int mt = 0; mt < 4; mt++) {
            int row0 = bm + wm * 64 + mt * 16 + g;
#pragma unroll
            for (int nt = 0; nt < NT; nt++) {
                int col = bn + wn * (BN / 4) + nt * 8 + t4 * 2;
                float d0 = acc[mt][nt][0], d1 = acc[mt][nt][1];
                float d2 = acc[mt][nt][2], d3 = acc[mt][nt][3];
                if (MODE == 1 || MODE == 2 || MODE == 5) {
                    float b0 = bias[col], b1 = bias[col + 1];
                    d0 += b0; d1 += b1; d2 += b0; d3 += b1;
                    if (MODE == 1 || MODE == 5) {
                        d0 = leaky(d0); d1 = leaky(d1);
                        d2 = leaky(d2); d3 = leaky(d3);
                    }
                }
                if (row0 < M) *(float2*)(C + (size_t)row0 * N + col) = make_float2(d0, d1);
                if (row0 + 8 < M) *(float2*)(C + (size_t)(row0 + 8) * N + col) = make_float2(d2, d3);
            }
        }
    }
}

// ---------------- misc small kernels ----------------
__global__ void kzero_f(float* p, int n) {
    int i = blockIdx.x * blockDim.x + threadIdx.x;
    if (i < n) p[i] = 0.f;
}
__global__ void k_zero_state(int NN, int E, int NQ) {
    int t = blockIdx.x * blockDim.x + threadIdx.x;
    if (t < NN) { g_segmax[t] = 0u; g_denom[t] = 0.f; }
    if (t < E)  { g_keep[t] = 0; g_logits[t] = 0.f; }
    if (t < NQ) g_qcnt[t] = 0;
}

// generic fp32 -> split fp16 (hi/lo), n4 = n/4
__global__ void k_split(const float* __restrict__ src, __half* __restrict__ hi,
                        __half* __restrict__ lo, int n4) {
    int i = blockIdx.x * blockDim.x + threadIdx.x;
    if (i >= n4) return;
    float4 v = ((const float4*)src)[i];
    __half h0, h1, h2, h3, l0, l1, l2, l3;
    split_h(v.x, h0, l0); split_h(v.y, h1, l1);
    split_h(v.z, h2, l2); split_h(v.w, h3, l3);
    ((__half2*)hi)[i * 2 + 0] = __halves2half2(h0, h1);
    ((__half2*)hi)[i * 2 + 1] = __halves2half2(h2, h3);
    ((__half2*)lo)[i * 2 + 0] = __halves2half2(l0, l1);
    ((__half2*)lo)[i * 2 + 1] = __halves2half2(l2, l3);
}

// weight repack + split
__global__ void k_prep(const float* __restrict__ Wl, const float* __restrict__ Wr) {
    int t = blockIdx.x * blockDim.x + threadIdx.x;
    if (t >= 512 * 512) return;
    int j = t >> 9, k = t & 511;
    float v = (j < 256) ? Wl[(size_t)j * 512 + k] : Wr[(size_t)(j - 256) * 512 + k];
    __half h, l;
    split_h(v, h, l);
    if (k < 128)      { g_WnodeH[j * 128 + k] = h;         g_WnodeL[j * 128 + k] = l; }
    else if (k < 256) { g_WrelH[j * 128 + k - 128] = h;    g_WrelL[j * 128 + k - 128] = l; }
    else              { g_WqH[j * 256 + k - 256] = h;      g_WqL[j * 256 + k - 256] = l; }
}
__global__ void k_qin(const float* __restrict__ qs, const float* __restrict__ qr,
                      const float* __restrict__ bl, const float* __restrict__ br, int NQ) {
    int t = blockIdx.x * blockDim.x + threadIdx.x;
    if (t < 512) g_bcat[t] = (t < 256) ? bl[t] : br[t - 256];
    if (t >= NQ * 256) return;
    int q = t >> 8, k = t & 255;
    float v = (k < 128) ? qs[q * 128 + k] : qr[q * 128 + (k - 128)];
    __half h, l;
    split_h(v, h, l);
    g_QinH[t] = h;
    g_QinL[t] = l;
}

// segment max over logits
__global__ void k_segmax(const int* __restrict__ idx_i, int E) {
    int e = blockIdx.x * blockDim.x + threadIdx.x;
    if (e >= E) return;
    atomicMax(&g_segmax[idx_i[e]], f2mono(g_logits[e]));
}
__global__ void k_ex(const int* __restrict__ idx_i, int E) {
    int e = blockIdx.x * blockDim.x + threadIdx.x;
    if (e >= E) return;
    int i = idx_i[e];
    float m = mono2f(g_segmax[i]);
    float ex = expf(g_logits[e] - m);
    g_ex[e] = ex;
    atomicAdd(&g_denom[i], ex);
}
// score + per-query bucket append
__global__ void k_score(const int* __restrict__ idx_i, const int* __restrict__ qidx,
                        const float* __restrict__ visited, int E) {
    int e = blockIdx.x * blockDim.x + threadIdx.x;
    if (e >= E) return;
    int i = idx_i[e];
    float a = g_ex[e] / g_denom[i];
    g_attn[e] = a;
    float sc = a * visited[i];
    g_scoreE[e] = sc;
    int q = qidx[e];
    int p = atomicAdd(&g_qcnt[q], 1);
    if (p < QCAP) {
        g_qkey[q * QCAP + p] = __float_as_uint(sc);   // sc >= 0 -> bits monotonic
        g_qedge[q * QCAP + p] = e;
    }
}

// ---------------- per-query top-k: one block per query, smem radix select ----------------
__global__ __launch_bounds__(256) void k_select(const int* __restrict__ max_edges, int NQ) {
    __shared__ unsigned hist[256];
    __shared__ unsigned sprefix;
    __shared__ int skr;
    __shared__ int eqn;
    __shared__ int eqedge[1024];
    int q = blockIdx.x;
    if (q >= NQ) return;
    int n = min(g_qcnt[q], QCAP);
    int k = max_edges ? *max_edges : 1024;
    const unsigned* keys = g_qkey + (size_t)q * QCAP;
    const int* edges = g_qedge + (size_t)q * QCAP;

    if (n <= k) {            // whole group kept
        for (int t = threadIdx.x; t < n; t += 256) g_keep[edges[t]] = 1;
        return;
    }
    if (threadIdx.x == 0) { sprefix = 0u; skr = k; eqn = 0; }
    __syncthreads();
#pragma unroll
    for (int pass = 0; pass < 4; pass++) {
        int shift = 24 - pass * 8;
        hist[threadIdx.x] = 0u;
        __syncthreads();
        unsigned pref = sprefix;
        for (int t = threadIdx.x; t < n; t += 256) {
            unsigned u = keys[t];
            if (pass == 0 || (u >> (shift + 8)) == (pref >> (shift + 8)))
                atomicAdd(&hist[(u >> shift) & 255u], 1u);
        }
        __syncthreads();
        if (threadIdx.x == 0) {
            unsigned kr = (unsigned)skr, c = 0;
            for (int b = 255; b >= 0; b--) {
                unsigned h = hist[b];
                if (c + h >= kr) {
                    sprefix = pref | (((unsigned)b) << shift);
                    skr = (int)(kr - c);
                    break;
                }
                c += h;
            }
        }
        __syncthreads();
    }
    unsigned T = sprefix;
    int kr = skr;
    // keep strictly-greater; collect equals
    for (int t = threadIdx.x; t < n; t += 256) {
        unsigned u = keys[t];
        if (u > T) g_keep[edges[t]] = 1;
        else if (u == T) {
            int p = atomicAdd(&eqn, 1);
            if (p < 1024) eqedge[p] = edges[t];
        }
    }
    __syncthreads();
    int m = min(eqn, 1024);
    // stable tiebreak among equals: smallest original edge id wins
    for (int t = threadIdx.x; t < m; t += 256) {
        int me = eqedge[t];
        int cnt = 0;
        for (int jj = 0; jj < m; jj++) cnt += (eqedge[jj] < me);
        if (cnt < kr) g_keep[me] = 1;
    }
}

// ---------------- pruned aggregation (into zeroed g_agg) ----------------
__global__ void k_aggregate(const float* __restrict__ node_rep,
                            const int* __restrict__ idx_i, const int* __restrict__ idx_j,
                            float* __restrict__ out_score, int E) {
    int w = (blockIdx.x * blockDim.x + threadIdx.x) >> 5;
    int lane = threadIdx.x & 31;
    if (w >= E) return;
    if (!g_keep[w]) return;
    int i = idx_i[w], j = idx_j[w];
    if (lane == 0) atomicAdd(out_score + j, g_scoreE[w]);
    float a = g_attn[w];
    float4 h = *(const float4*)(node_rep + (size_t)i * D + lane * 4);
#if __CUDA_ARCH__ >= 900
    atomicAdd((float4*)(g_agg + (size_t)j * D + lane * 4),
              make_float4(a * h.x, a * h.y, a * h.z, a * h.w));
#else
    float* dst = g_agg + (size_t)j * D + lane * 4;
    atomicAdd(dst + 0, a * h.x);
    atomicAdd(dst + 1, a * h.y);
    atomicAdd(dst + 2, a * h.z);
    atomicAdd(dst + 3, a * h.w);
#endif
}

// ---------------- launch ----------------
extern "C" void kernel_launch(void* const* d_in, const int* in_sizes, int n_in,
                              void* d_out, int out_size) {
    const float* visited  = (const float*)d_in[0];
    const float* node_rep = (const float*)d_in[1];
    const float* qsrc     = (const float*)d_in[2];
    const float* qrel     = (const float*)d_in[3];
    const float* rel      = (const float*)d_in[4];
    const float* W_left   = (const float*)d_in[5];
    const float* b_left   = (const float*)d_in[6];
    const float* W_right  = (const float*)d_in[7];
    const float* b_right  = (const float*)d_in[8];
    const float* W_center = (const float*)d_in[9];
    const float* b_center = (const float*)d_in[10];
    const float* W_step   = (const float*)d_in[11];
    const float* b_step   = (const float*)d_in[12];
    const int* query_idx  = (const int*)d_in[13];
    const int* idx_i      = (const int*)d_in[14];
    const int* idx_j      = (const int*)d_in[15];
    const int* max_edges  = (n_in >= 17) ? (const int*)d_in[16] : nullptr;

    int NN = in_sizes[0];
    int E  = in_sizes[13];
    int NQ = in_sizes[2] / D;

    float* out_score = (float*)d_out;
    float* out_rep   = (float*)d_out + NN;

    void* p;
    cudaGetSymbolAddress(&p, g_Pnode);  float* Pnode  = (float*)p;
    cudaGetSymbolAddress(&p, g_Qc);     float* Qc     = (float*)p;
    cudaGetSymbolAddress(&p, g_bcat);   float* bcat   = (float*)p;
    cudaGetSymbolAddress(&p, g_L);      float* Lbuf   = (float*)p;
    cudaGetSymbolAddress(&p, g_agg);    float* agg    = (float*)p;
    cudaGetSymbolAddress(&p, g_WnodeH); __half* WnodeH = (__half*)p;
    cudaGetSymbolAddress(&p, g_WnodeL); __half* WnodeL = (__half*)p;
    cudaGetSymbolAddress(&p, g_WrelH);  __half* WrelH  = (__half*)p;
    cudaGetSymbolAddress(&p, g_WrelL);  __half* WrelL  = (__half*)p;
    cudaGetSymbolAddress(&p, g_WqH);    __half* WqH    = (__half*)p;
    cudaGetSymbolAddress(&p, g_WqL);    __half* WqL    = (__half*)p;
    cudaGetSymbolAddress(&p, g_WcH);    __half* WcH    = (__half*)p;
    cudaGetSymbolAddress(&p, g_WcL);    __half* WcL    = (__half*)p;
    cudaGetSymbolAddress(&p, g_WsH);    __half* WsH    = (__half*)p;
    cudaGetSymbolAddress(&p, g_WsL);    __half* WsL    = (__half*)p;
    cudaGetSymbolAddress(&p, g_QinH);   __half* QinH   = (__half*)p;
    cudaGetSymbolAddress(&p, g_QinL);   __half* QinL   = (__half*)p;
    cudaGetSymbolAddress(&p, g_NodeH);  __half* NodeH  = (__half*)p;
    cudaGetSymbolAddress(&p, g_NodeL);  __half* NodeL  = (__half*)p;
    cudaGetSymbolAddress(&p, g_RelH);   __half* RelH   = (__half*)p;
    cudaGetSymbolAddress(&p, g_RelL);   __half* RelL   = (__half*)p;
    cudaGetSymbolAddress(&p, g_R1H);    __half* R1H    = (__half*)p;
    cudaGetSymbolAddress(&p, g_R1L);    __half* R1L    = (__half*)p;

    static int smem_set = 0;
    if (!smem_set) {
        cudaFuncSetAttribute(gemm_f16<0, 128>, cudaFuncAttributeMaxDynamicSharedMemorySize, SMEMB(128));
        cudaFuncSetAttribute(gemm_f16<2, 128>, cudaFuncAttributeMaxDynamicSharedMemorySize, SMEMB(128));
        cudaFuncSetAttribute(gemm_f16<3, 256>, cudaFuncAttributeMaxDynamicSharedMemorySize, SMEMB(256));
        cudaFuncSetAttribute(gemm_f16<4, 256>, cudaFuncAttributeMaxDynamicSharedMemorySize, SMEMB(256));
        cudaFuncSetAttribute(gemm_f16<5, 128>, cudaFuncAttributeMaxDynamicSharedMemorySize, SMEMB(128));
        smem_set = 1;
    }

    const int T = 256;
    // --- init state ---
    kzero_f<<<(NN + T - 1) / T, T>>>(out_score, NN);
    kzero_f<<<((size_t)NN * D + T - 1) / T, T>>>(agg, NN * D);
    {
        int mx = NN > E ? NN : E;
        k_zero_state<<<(mx + T - 1) / T, T>>>(NN, E, NQ);
    }
    // --- operand prep ---
    k_prep<<<(512 * 512 + T - 1) / T, T>>>(W_left, W_right);
    k_split<<<(256 * 256 / 4 + T - 1) / T, T>>>(W_center, WcH, WcL, 256 * 256 / 4);
    k_split<<<(128 * 128 / 4 + T - 1) / T, T>>>(W_step, WsH, WsL, 128 * 128 / 4);
    k_qin<<<(NQ * 256 + T - 1) / T, T>>>(qsrc, qrel, b_left, b_right, NQ);
    k_split<<<((NN * 128 / 4) + T - 1) / T, T>>>(node_rep, NodeH, NodeL, NN * 128 / 4);
    k_split<<<((E * 128 / 4) + T - 1) / T, T>>>(rel, RelH, RelL, E * 128 / 4);
    // --- Qc GEMM: bias-folded query term ---
    gemm_f16<2, 128><<<dim3(4, (NQ + 127) / 128), T, SMEMB(128)>>>(
        QinH, QinL, WqH, WqL, Qc, bcat, NQ, 512, 256,
        nullptr, nullptr, nullptr, nullptr, nullptr, nullptr, nullptr, nullptr, nullptr);
    // --- Pnode GEMM ---
    gemm_f16<0, 128><<<dim3(4, (NN + 127) / 128), T, SMEMB(128)>>>(
        NodeH, NodeL, WnodeH, WnodeL, Pnode, nullptr, NN, 512, 128,
        nullptr, nullptr, nullptr, nullptr, nullptr, nullptr, nullptr, nullptr, nullptr);
    // --- Prel GEMM (BN=256), fused assemble epilogue ---
    gemm_f16<3, 256><<<dim3(2, (E + 127) / 128), T, SMEMB(256)>>>(
        RelH, RelL, WrelH, WrelL, nullptr, nullptr, E, 512, 128,
        idx_i, idx_j, query_idx, Pnode, Qc, Lbuf, R1H, R1L, nullptr);
    // --- center GEMM (BN=256), fused logits epilogue ---
    gemm_f16<4, 256><<<dim3(1, (E + 127) / 128), T, SMEMB(256)>>>(
        R1H, R1L, WcH, WcL, nullptr, b_center, E, 256, 256,
        nullptr, nullptr, nullptr, nullptr, nullptr, nullptr, nullptr, nullptr, Lbuf);
    // --- segment softmax + score/bucket ---
    k_segmax<<<(E + T - 1) / T, T>>>(idx_i, E);
    k_ex<<<(E + T - 1) / T, T>>>(idx_i, E);
    k_score<<<(E + T - 1) / T, T>>>(idx_i, query_idx, visited, E);
    // --- per-query top-k: one block per query, smem radix select ---
    k_select<<<NQ, 256>>>(max_edges, NQ);
    // --- aggregation into zeroed g_agg ---
    k_aggregate<<<((size_t)E * 32 + T - 1) / T, T>>>(node_rep, idx_i, idx_j, out_score, E);
    // --- step GEMM: A = node_rep + agg, split in-register; bias + leaky ---
    gemm_f16<5, 128><<<dim3(1, (NN + 127) / 128), T, SMEMB(128)>>>(
        nullptr, nullptr, WsH, WsL, out_rep, b_step, NN, 128, 128,
        nullptr, nullptr, nullptr, node_rep, agg, nullptr, nullptr, nullptr, nullptr);
    (void)out_size;
}

// round 16
// speedup vs baseline: 1.1310x; 1.1310x over previous
#include <cuda_runtime.h>
#include <cuda_fp16.h>
#include <cstdint>
#include <math.h>

#define D 128
#define NMAX 100352
#define EMAX 131072
#define NQMAX 128
#define QCAP 4096

// ---------------- static scratch (allocation-free rule) ----------------
__device__ float    g_Qc   [NQMAX * 512];       // query combined (+bias folded)
__device__ float    g_bcat [512];               // [b_left ; b_right]
__device__ float    g_Pnode[NMAX * 512];
__device__ float    g_L  [EMAX * 256];
__device__ float    g_logits[EMAX];
__device__ float    g_ex[EMAX];
__device__ float    g_attn[EMAX];
__device__ float    g_scoreE[EMAX];
__device__ unsigned g_segmax[NMAX];
__device__ float    g_denom[NMAX];
__device__ float    g_agg[NMAX * D];            // attention-weighted message sum (zeroed)
__device__ int      g_keep[EMAX];               // final per-edge keep flag (zeroed)
__device__ int      g_qcnt[NQMAX];              // per-query bucket counts (zeroed)
__device__ unsigned g_qkey [NQMAX * QCAP];      // per-query score keys
__device__ int      g_qedge[NQMAX * QCAP];      // per-query edge ids

// split fp16 operand buffers (hi/lo)
__device__ __align__(128) __half g_WnodeH[512 * 128], g_WnodeL[512 * 128];
__device__ __align__(128) __half g_WrelH [512 * 128], g_WrelL [512 * 128];
__device__ __align__(128) __half g_WqH   [512 * 256], g_WqL   [512 * 256];
__device__ __align__(128) __half g_WcH   [256 * 256], g_WcL   [256 * 256];
__device__ __align__(128) __half g_WsH   [128 * 128], g_WsL   [128 * 128];
__device__ __align__(128) __half g_QinH  [NQMAX * 256], g_QinL[NQMAX * 256];
__device__ __align__(128) __half g_NodeH [NMAX * 128], g_NodeL[NMAX * 128];
__device__ __align__(128) __half g_RelH  [EMAX * 128], g_RelL [EMAX * 128];
__device__ __align__(128) __half g_R1H   [EMAX * 256], g_R1L  [EMAX * 256];

__device__ __forceinline__ float leaky(float x) { return x > 0.f ? x : 0.01f * x; }
__device__ __forceinline__ unsigned f2mono(float f) {
    unsigned b = __float_as_uint(f);
    return (b & 0x80000000u) ? ~b : (b | 0x80000000u);
}
__device__ __forceinline__ float mono2f(unsigned u) {
    return (u & 0x80000000u) ? __uint_as_float(u & 0x7fffffffu) : __uint_as_float(~u);
}
__device__ __forceinline__ uint32_t smem_u32(const void* p) {
    uint32_t a;
    asm("{ .reg .u64 t; cvta.to.shared.u64 t, %1; cvt.u32.u64 %0, t; }" : "=r"(a) : "l"(p));
    return a;
}
__device__ __forceinline__ void split_h(float v, __half& h, __half& l) {
    h = __float2half_rn(v);
    l = __float2half_rn(v - __half2float(h));
}
__device__ __forceinline__ void ldsm4(uint32_t* r, uint32_t addr) {
    asm volatile("ldmatrix.sync.aligned.m8n8.x4.shared.b16 {%0,%1,%2,%3}, [%4];"
                 : "=r"(r[0]), "=r"(r[1]), "=r"(r[2]), "=r"(r[3]) : "r"(addr));
}
__device__ __forceinline__ void mma_f16(float* d, const uint32_t* a, const uint32_t* b) {
    asm volatile(
        "mma.sync.aligned.m16n8k16.row.col.f32.f16.f16.f32 "
        "{%0,%1,%2,%3}, {%4,%5,%6,%7}, {%8,%9}, {%0,%1,%2,%3};"
        : "+f"(d[0]), "+f"(d[1]), "+f"(d[2]), "+f"(d[3])
        : "r"(a[0]), "r"(a[1]), "r"(a[2]), "r"(a[3]), "r"(b[0]), "r"(b[1]));
}

// ================= fp16 3-pass split GEMM: C[M,N] = A[M,K] @ B[N,K]^T =================
// MODE 0: plain store   1: bias+leaky store   2: bias store
// MODE 3: assemble-fused epilogue (Prel GEMM): gathers Pnode/Qc, leaky, writes L + split R1
// MODE 4: logits-fused epilogue (center GEMM): partial dot with L, atomicAdd into g_logits
// MODE 5: A = fp32(Pn + Qc2) summed+split in-register (step GEMM); bias+leaky store
#define ROWH 40
#define TILE_H (128 * ROWH)
#define STAGE_H (4 * TILE_H)
#define GEMM_SMEM_BYTES (2 * STAGE_H * 2)  // 81920 bytes
template <int MODE>
__global__ __launch_bounds__(256) void gemm_f16(const __half* __restrict__ Ah,
                                                const __half* __restrict__ Al,
                                                const __half* __restrict__ Bh,
                                                const __half* __restrict__ Bl,
                                                float* __restrict__ C,
                                                const float* __restrict__ bias,
                                                int M, int N, int K,
                                                const int* __restrict__ idx_i,
                                                const int* __restrict__ idx_j,
                                                const int* __restrict__ qidx,
                                                const float* __restrict__ Pn,
                                                const float* __restrict__ Qc2,
                                                float* __restrict__ outL,
                                                __half* __restrict__ outRH,
                                                __half* __restrict__ outRL,
                                                const float* __restrict__ Lbuf) {
    extern __shared__ __align__(128) __half sm[];
    const int tid = threadIdx.x, lane = tid & 31, wid = tid >> 5;
    const int wm = wid & 1, wn = wid >> 1;
    const int bm = blockIdx.y * 128, bn = blockIdx.x * 128;
    const int rl = lane & 7, q = lane >> 3;

    float acc[4][4][4];
#pragma unroll
    for (int mt = 0; mt < 4; mt++)
#pragma unroll
        for (int nt = 0; nt < 4; nt++)
#pragma unroll
            for (int r = 0; r < 4; r++) acc[mt][nt][r] = 0.f;

    auto load_stage = [&](int st, int kc) {
        if constexpr (MODE == 5) {
#pragma unroll
            for (int i = 0; i < 4; i++) {
                int ch = tid + i * 256;
                int t2 = ch >> 9, r = (ch >> 2) & 127, seg = ch & 3;
                const __half* src = (t2 == 0 ? Bh : Bl) + (size_t)(bn + r) * K + kc + seg * 8;
                uint32_t dst = smem_u32(sm + st * STAGE_H + (2 + t2) * TILE_H + r * ROWH + seg * 8);
                asm volatile("cp.async.cg.shared.global [%0], [%1], 16, 16;"
                             :: "r"(dst), "l"(src));
            }
            asm volatile("cp.async.commit_group;" ::: "memory");
#pragma unroll
            for (int i = 0; i < 4; i++) {
                int s = tid + i * 256;
                int r = s >> 3, c4 = (s & 7) * 4;
                int gm = bm + r;
                float4 va = make_float4(0.f, 0.f, 0.f, 0.f), vb = va;
                if (gm < M) {
                    va = *(const float4*)(Pn + (size_t)gm * K + kc + c4);
                    vb = *(const float4*)(Qc2 + (size_t)gm * K + kc + c4);
                }
                float f0 = va.x + vb.x, f1 = va.y + vb.y, f2 = va.z + vb.z, f3 = va.w + vb.w;
                __half h0, h1, h2, h3, l0, l1, l2, l3;
                split_h(f0, h0, l0); split_h(f1, h1, l1);
                split_h(f2, h2, l2); split_h(f3, h3, l3);
                __half* ah = sm + st * STAGE_H + r * ROWH + c4;
                __half* al = sm + st * STAGE_H + TILE_H + r * ROWH + c4;
                *(__half2*)(ah) = __halves2half2(h0, h1);
                *(__half2*)(ah + 2) = __halves2half2(h2, h3);
                *(__half2*)(al) = __halves2half2(l0, l1);
                *(__half2*)(al + 2) = __halves2half2(l2, l3);
            }
        } else {
#pragma unroll
            for (int i = 0; i < 8; i++) {
                int ch = tid + i * 256;
                int tile = ch >> 9, r = (ch >> 2) & 127, seg = ch & 3;
                const __half* src;
                int sz = 16;
                if (tile < 2) {
                    int row = bm + r;
                    int rc = row < M ? row : 0;
                    sz = row < M ? 16 : 0;
                    src = (tile == 0 ? Ah : Al) + (size_t)rc * K + kc + seg * 8;
                } else {
                    int row = bn + r;
                    src = (tile == 2 ? Bh : Bl) + (size_t)row * K + kc + seg * 8;
                }
                uint32_t dst = smem_u32(sm + st * STAGE_H + tile * TILE_H + r * ROWH + seg * 8);
                asm volatile("cp.async.cg.shared.global [%0], [%1], 16, %2;"
                             :: "r"(dst), "l"(src), "r"(sz));
            }
            asm volatile("cp.async.commit_group;" ::: "memory");
        }
    };

    const int nch = K >> 5;
    load_stage(0, 0);

    for (int c = 0; c < nch; c++) {
        if (c + 1 < nch) {
            load_stage((c + 1) & 1, (c + 1) << 5);
            asm volatile("cp.async.wait_group 1;" ::: "memory");
        } else {
            asm volatile("cp.async.wait_group 0;" ::: "memory");
        }
        __syncthreads();

        const __half* base = sm + (c & 1) * STAGE_H;
        uint32_t aAh = smem_u32(base);
        uint32_t aAl = smem_u32(base + TILE_H);
        uint32_t aBh = smem_u32(base + 2 * TILE_H);
        uint32_t aBl = smem_u32(base + 3 * TILE_H);

#pragma unroll
        for (int ks = 0; ks < 2; ks++) {
            uint32_t ah[4][4], al[4][4], bh[4][2], bl[4][2];
#pragma unroll
            for (int mt = 0; mt < 4; mt++) {
                uint32_t off = ((wm * 64 + mt * 16 + (q & 1) * 8 + rl) * ROWH +
                                ks * 16 + (q >> 1) * 8) * 2;
                ldsm4(ah[mt], aAh + off);
                ldsm4(al[mt], aAl + off);
            }
#pragma unroll
            for (int p = 0; p < 2; p++) {
                uint32_t off = ((wn * 32 + p * 16 + (q >> 1) * 8 + rl) * ROWH +
                                ks * 16 + (q & 1) * 8) * 2;
                uint32_t t[4];
                ldsm4(t, aBh + off);
                bh[2 * p][0] = t[0]; bh[2 * p][1] = t[1];
                bh[2 * p + 1][0] = t[2]; bh[2 * p + 1][1] = t[3];
                ldsm4(t, aBl + off);
                bl[2 * p][0] = t[0]; bl[2 * p][1] = t[1];
                bl[2 * p + 1][0] = t[2]; bl[2 * p + 1][1] = t[3];
            }
#pragma unroll
            for (int mt = 0; mt < 4; mt++)
#pragma unroll
                for (int nt = 0; nt < 4; nt++) {
                    mma_f16(acc[mt][nt], ah[mt], bh[nt]);
                    mma_f16(acc[mt][nt], ah[mt], bl[nt]);
                    mma_f16(acc[mt][nt], al[mt], bh[nt]);
                }
        }
        __syncthreads();
    }

    // ---- epilogues ----
    const int g = lane >> 2, t4 = lane & 3;

    if constexpr (MODE == 3) {
        int* si = (int*)sm;
        if (tid < 128) {
            int e = bm + tid;
            si[tid] = idx_i[e];
            si[128 + tid] = idx_j[e];
            si[256 + tid] = qidx[e];
        }
        __syncthreads();
#pragma unroll
        for (int mt = 0; mt < 4; mt++) {
            int rl0 = wm * 64 + mt * 16 + g;
            int i0 = si[rl0], j0 = si[128 + rl0], q0 = si[256 + rl0];
            int i1 = si[rl0 + 8], j1 = si[128 + rl0 + 8], q1 = si[256 + rl0 + 8];
            size_t e0 = (size_t)bm + rl0, e1 = e0 + 8;
#pragma unroll
            for (int nt = 0; nt < 4; nt++) {
                int col = bn + wn * 32 + nt * 8 + t4 * 2;
                bool left = col < 256;
                int b0 = left ? i0 : j0, b1 = left ? i1 : j1;
                float2 pn0 = *(const float2*)(Pn + (size_t)b0 * 512 + col);
                float2 qc0 = *(const float2*)(Qc2 + (size_t)q0 * 512 + col);
                float2 pn1 = *(const float2*)(Pn + (size_t)b1 * 512 + col);
                float2 qc1 = *(const float2*)(Qc2 + (size_t)q1 * 512 + col);
                float v0 = leaky(acc[mt][nt][0] + pn0.x + qc0.x);
                float v1 = leaky(acc[mt][nt][1] + pn0.y + qc0.y);
                float v2 = leaky(acc[mt][nt][2] + pn1.x + qc1.x);
                float v3 = leaky(acc[mt][nt][3] + pn1.y + qc1.y);
                if (left) {
                    *(float2*)(outL + e0 * 256 + col) = make_float2(v0, v1);
                    *(float2*)(outL + e1 * 256 + col) = make_float2(v2, v3);
                } else {
                    __half h0, l0, h1, l1, h2, l2, h3, l3;
                    split_h(v0, h0, l0); split_h(v1, h1, l1);
                    split_h(v2, h2, l2); split_h(v3, h3, l3);
                    size_t o0 = e0 * 256 + col - 256, o1 = e1 * 256 + col - 256;
                    *(__half2*)(outRH + o0) = __halves2half2(h0, h1);
                    *(__half2*)(outRL + o0) = __halves2half2(l0, l1);
                    *(__half2*)(outRH + o1) = __halves2half2(h2, h3);
                    *(__half2*)(outRL + o1) = __halves2half2(l2, l3);
                }
            }
        }
    } else if constexpr (MODE == 4) {
#pragma unroll
        for (int mt = 0; mt < 4; mt++) {
            int r0 = bm + wm * 64 + mt * 16 + g;
            float p0 = 0.f, p1 = 0.f;
#pragma unroll
            for (int nt = 0; nt < 4; nt++) {
                int col = bn + wn * 32 + nt * 8 + t4 * 2;
                float b0 = bias[col], b1 = bias[col + 1];
                float2 l0 = *(const float2*)(Lbuf + (size_t)r0 * 256 + col);
                float2 l1 = *(const float2*)(Lbuf + (size_t)(r0 + 8) * 256 + col);
                p0 = fmaf(l0.x, acc[mt][nt][0] + b0, p0);
                p0 = fmaf(l0.y, acc[mt][nt][1] + b1, p0);
                p1 = fmaf(l1.x, acc[mt][nt][2] + b0, p1);
                p1 = fmaf(l1.y, acc[mt][nt][3] + b1, p1);
            }
            p0 += __shfl_xor_sync(0xffffffffu, p0, 1);
            p0 += __shfl_xor_sync(0xffffffffu, p0, 2);
            p1 += __shfl_xor_sync(0xffffffffu, p1, 1);
            p1 += __shfl_xor_sync(0xffffffffu, p1, 2);
            if (t4 == 0) {
                atomicAdd(&g_logits[r0], p0);
                atomicAdd(&g_logits[r0 + 8], p1);
            }
        }
    } else {
#pragma unroll
        for (int mt = 0; mt < 4; mt++) {
            int row0 = bm + wm * 64 + mt * 16 + g;
#pragma unroll
            for (int nt = 0; nt < 4; nt++) {
                int col = bn + wn * 32 + nt * 8 + t4 * 2;
                float d0 = acc[mt][nt][0], d1 = acc[mt][nt][1];
                float d2 = acc[mt][nt][2], d3 = acc[mt][nt][3];
                if (MODE == 1 || MODE == 2 || MODE == 5) {
                    float b0 = bias[col], b1 = bias[col + 1];
                    d0 += b0; d1 += b1; d2 += b0; d3 += b1;
                    if (MODE == 1 || MODE == 5) {
                        d0 = leaky(d0); d1 = leaky(d1);
                        d2 = leaky(d2); d3 = leaky(d3);
                    }
                }
                if (row0 < M) *(float2*)(C + (size_t)row0 * N + col) = make_float2(d0, d1);
                if (row0 + 8 < M) *(float2*)(C + (size_t)(row0 + 8) * N + col) = make_float2(d2, d3);
            }
        }
    }
}

// ---------------- merged init: zero all state in one launch ----------------
__global__ void k_init(float* __restrict__ out_score, int NN, int E, int NQ) {
    int gs = gridDim.x * blockDim.x;
    int gtid = blockIdx.x * blockDim.x + threadIdx.x;
    for (int t = gtid; t < NN * D; t += gs) g_agg[t] = 0.f;
    for (int t = gtid; t < NN; t += gs) {
        g_segmax[t] = 0u;
        g_denom[t] = 0.f;
        out_score[t] = 0.f;
    }
    for (int t = gtid; t < E; t += gs) {
        g_keep[t] = 0;
        g_logits[t] = 0.f;
    }
    for (int t = gtid; t < NQ; t += gs) g_qcnt[t] = 0;
}

// ---------------- merged operand prep (weights + query) ----------------
__global__ void k_prep_all(const float* __restrict__ Wl, const float* __restrict__ Wr,
                           const float* __restrict__ Wc, const float* __restrict__ Ws,
                           const float* __restrict__ qs, const float* __restrict__ qr,
                           const float* __restrict__ bl, const float* __restrict__ br,
                           int NQ) {
    int gs = gridDim.x * blockDim.x;
    int gtid = blockIdx.x * blockDim.x + threadIdx.x;
    __half h, l;
    // W_left / W_right repack+split
    for (int t = gtid; t < 512 * 512; t += gs) {
        int j = t >> 9, k = t & 511;
        float v = (j < 256) ? Wl[(size_t)j * 512 + k] : Wr[(size_t)(j - 256) * 512 + k];
        split_h(v, h, l);
        if (k < 128)      { g_WnodeH[j * 128 + k] = h;       g_WnodeL[j * 128 + k] = l; }
        else if (k < 256) { g_WrelH[j * 128 + k - 128] = h;  g_WrelL[j * 128 + k - 128] = l; }
        else              { g_WqH[j * 256 + k - 256] = h;    g_WqL[j * 256 + k - 256] = l; }
    }
    // W_center split
    for (int t = gtid; t < 256 * 256; t += gs) {
        split_h(Wc[t], h, l);
        g_WcH[t] = h; g_WcL[t] = l;
    }
    // W_step split
    for (int t = gtid; t < 128 * 128; t += gs) {
        split_h(Ws[t], h, l);
        g_WsH[t] = h; g_WsL[t] = l;
    }
    // query concat + split
    for (int t = gtid; t < NQ * 256; t += gs) {
        int q = t >> 8, k = t & 255;
        float v = (k < 128) ? qs[q * 128 + k] : qr[q * 128 + (k - 128)];
        split_h(v, h, l);
        g_QinH[t] = h; g_QinL[t] = l;
    }
    if (gtid < 512) g_bcat[gtid] = (gtid < 256) ? bl[gtid] : br[gtid - 256];
}

// ---------------- merged big splits (node_rep + rel) ----------------
__global__ void k_split_big(const float* __restrict__ node_rep, const float* __restrict__ rel,
                            int NN, int E) {
    int gs = gridDim.x * blockDim.x;
    int gtid = blockIdx.x * blockDim.x + threadIdx.x;
    int n4a = NN * 32;  // NN*128/4
    int n4b = E * 32;
    __half h0, h1, h2, h3, l0, l1, l2, l3;
    for (int i = gtid; i < n4a; i += gs) {
        float4 v = ((const float4*)node_rep)[i];
        split_h(v.x, h0, l0); split_h(v.y, h1, l1);
        split_h(v.z, h2, l2); split_h(v.w, h3, l3);
        ((__half2*)g_NodeH)[i * 2 + 0] = __halves2half2(h0, h1);
        ((__half2*)g_NodeH)[i * 2 + 1] = __halves2half2(h2, h3);
        ((__half2*)g_NodeL)[i * 2 + 0] = __halves2half2(l0, l1);
        ((__half2*)g_NodeL)[i * 2 + 1] = __halves2half2(l2, l3);
    }
    for (int i = gtid; i < n4b; i += gs) {
        float4 v = ((const float4*)rel)[i];
        split_h(v.x, h0, l0); split_h(v.y, h1, l1);
        split_h(v.z, h2, l2); split_h(v.w, h3, l3);
        ((__half2*)g_RelH)[i * 2 + 0] = __halves2half2(h0, h1);
        ((__half2*)g_RelH)[i * 2 + 1] = __halves2half2(h2, h3);
        ((__half2*)g_RelL)[i * 2 + 0] = __halves2half2(l0, l1);
        ((__half2*)g_RelL)[i * 2 + 1] = __halves2half2(l2, l3);
    }
}

// segment max over logits
__global__ void k_segmax(const int* __restrict__ idx_i, int E) {
    int e = blockIdx.x * blockDim.x + threadIdx.x;
    if (e >= E) return;
    atomicMax(&g_segmax[idx_i[e]], f2mono(g_logits[e]));
}
__global__ void k_ex(const int* __restrict__ idx_i, int E) {
    int e = blockIdx.x * blockDim.x + threadIdx.x;
    if (e >= E) return;
    int i = idx_i[e];
    float m = mono2f(g_segmax[i]);
    float ex = expf(g_logits[e] - m);
    g_ex[e] = ex;
    atomicAdd(&g_denom[i], ex);
}
// score + per-query bucket append
__global__ void k_score(const int* __restrict__ idx_i, const int* __restrict__ qidx,
                        const float* __restrict__ visited, int E) {
    int e = blockIdx.x * blockDim.x + threadIdx.x;
    if (e >= E) return;
    int i = idx_i[e];
    float a = g_ex[e] / g_denom[i];
    g_attn[e] = a;
    float sc = a * visited[i];
    g_scoreE[e] = sc;
    int q = qidx[e];
    int p = atomicAdd(&g_qcnt[q], 1);
    if (p < QCAP) {
        g_qkey[q * QCAP + p] = __float_as_uint(sc);   // sc >= 0 -> bits monotonic
        g_qedge[q * QCAP + p] = e;
    }
}

// ---------------- per-query top-k: one block per query, smem radix select ----------------
__global__ __launch_bounds__(256) void k_select(const int* __restrict__ max_edges, int NQ) {
    __shared__ unsigned hist[256];
    __shared__ unsigned sprefix;
    __shared__ int skr;
    __shared__ int eqn;
    __shared__ int eqedge[1024];
    int q = blockIdx.x;
    if (q >= NQ) return;
    int n = min(g_qcnt[q], QCAP);
    int k = max_edges ? *max_edges : 1024;
    const unsigned* keys = g_qkey + (size_t)q * QCAP;
    const int* edges = g_qedge + (size_t)q * QCAP;

    if (n <= k) {            // whole group kept
        for (int t = threadIdx.x; t < n; t += 256) g_keep[edges[t]] = 1;
        return;
    }
    if (threadIdx.x == 0) { sprefix = 0u; skr = k; eqn = 0; }
    __syncthreads();
#pragma unroll
    for (int pass = 0; pass < 4; pass++) {
        int shift = 24 - pass * 8;
        hist[threadIdx.x] = 0u;
        __syncthreads();
        unsigned pref = sprefix;
        for (int t = threadIdx.x; t < n; t += 256) {
            unsigned u = keys[t];
            if (pass == 0 || (u >> (shift + 8)) == (pref >> (shift + 8)))
                atomicAdd(&hist[(u >> shift) & 255u], 1u);
        }
        __syncthreads();
        if (threadIdx.x == 0) {
            unsigned kr = (unsigned)skr, c = 0;
            for (int b = 255; b >= 0; b--) {
                unsigned h = hist[b];
                if (c + h >= kr) {
                    sprefix = pref | (((unsigned)b) << shift);
                    skr = (int)(kr - c);
                    break;
                }
                c += h;
            }
        }
        __syncthreads();
    }
    unsigned T = sprefix;
    int kr = skr;
    // keep strictly-greater; collect equals
    for (int t = threadIdx.x; t < n; t += 256) {
        unsigned u = keys[t];
        if (u > T) g_keep[edges[t]] = 1;
        else if (u == T) {
            int p = atomicAdd(&eqn, 1);
            if (p < 1024) eqedge[p] = edges[t];
        }
    }
    __syncthreads();
    int m = min(eqn, 1024);
    // stable tiebreak among equals: smallest original edge id wins
    for (int t = threadIdx.x; t < m; t += 256) {
        int me = eqedge[t];
        int cnt = 0;
        for (int jj = 0; jj < m; jj++) cnt += (eqedge[jj] < me);
        if (cnt < kr) g_keep[me] = 1;
    }
}

// ---------------- pruned aggregation (into zeroed g_agg) ----------------
__global__ void k_aggregate(const float* __restrict__ node_rep,
                            const int* __restrict__ idx_i, const int* __restrict__ idx_j,
                            float* __restrict__ out_score, int E) {
    int w = (blockIdx.x * blockDim.x + threadIdx.x) >> 5;
    int lane = threadIdx.x & 31;
    if (w >= E) return;
    if (!g_keep[w]) return;
    int i = idx_i[w], j = idx_j[w];
    if (lane == 0) atomicAdd(out_score + j, g_scoreE[w]);
    float a = g_attn[w];
    float4 h = *(const float4*)(node_rep + (size_t)i * D + lane * 4);
#if __CUDA_ARCH__ >= 900
    atomicAdd((float4*)(g_agg + (size_t)j * D + lane * 4),
              make_float4(a * h.x, a * h.y, a * h.z, a * h.w));
#else
    float* dst = g_agg + (size_t)j * D + lane * 4;
    atomicAdd(dst + 0, a * h.x);
    atomicAdd(dst + 1, a * h.y);
    atomicAdd(dst + 2, a * h.z);
    atomicAdd(dst + 3, a * h.w);
#endif
}

// ---------------- launch ----------------
extern "C" void kernel_launch(void* const* d_in, const int* in_sizes, int n_in,
                              void* d_out, int out_size) {
    const float* visited  = (const float*)d_in[0];
    const float* node_rep = (const float*)d_in[1];
    const float* qsrc     = (const float*)d_in[2];
    const float* qrel     = (const float*)d_in[3];
    const float* rel      = (const float*)d_in[4];
    const float* W_left   = (const float*)d_in[5];
    const float* b_left   = (const float*)d_in[6];
    const float* W_right  = (const float*)d_in[7];
    const float* b_right  = (const float*)d_in[8];
    const float* W_center = (const float*)d_in[9];
    const float* b_center = (const float*)d_in[10];
    const float* W_step   = (const float*)d_in[11];
    const float* b_step   = (const float*)d_in[12];
    const int* query_idx  = (const int*)d_in[13];
    const int* idx_i      = (const int*)d_in[14];
    const int* idx_j      = (const int*)d_in[15];
    const int* max_edges  = (n_in >= 17) ? (const int*)d_in[16] : nullptr;

    int NN = in_sizes[0];
    int E  = in_sizes[13];
    int NQ = in_sizes[2] / D;

    float* out_score = (float*)d_out;
    float* out_rep   = (float*)d_out + NN;

    void* p;
    cudaGetSymbolAddress(&p, g_Pnode);  float* Pnode  = (float*)p;
    cudaGetSymbolAddress(&p, g_Qc);     float* Qc     = (float*)p;
    cudaGetSymbolAddress(&p, g_bcat);   float* bcat   = (float*)p;
    cudaGetSymbolAddress(&p, g_L);      float* Lbuf   = (float*)p;
    cudaGetSymbolAddress(&p, g_agg);    float* agg    = (float*)p;
    cudaGetSymbolAddress(&p, g_WnodeH); __half* WnodeH = (__half*)p;
    cudaGetSymbolAddress(&p, g_WnodeL); __half* WnodeL = (__half*)p;
    cudaGetSymbolAddress(&p, g_WrelH);  __half* WrelH  = (__half*)p;
    cudaGetSymbolAddress(&p, g_WrelL);  __half* WrelL  = (__half*)p;
    cudaGetSymbolAddress(&p, g_WqH);    __half* WqH    = (__half*)p;
    cudaGetSymbolAddress(&p, g_WqL);    __half* WqL    = (__half*)p;
    cudaGetSymbolAddress(&p, g_WcH);    __half* WcH    = (__half*)p;
    cudaGetSymbolAddress(&p, g_WcL);    __half* WcL    = (__half*)p;
    cudaGetSymbolAddress(&p, g_WsH);    __half* WsH    = (__half*)p;
    cudaGetSymbolAddress(&p, g_WsL);    __half* WsL    = (__half*)p;
    cudaGetSymbolAddress(&p, g_QinH);   __half* QinH   = (__half*)p;
    cudaGetSymbolAddress(&p, g_QinL);   __half* QinL   = (__half*)p;
    cudaGetSymbolAddress(&p, g_NodeH);  __half* NodeH  = (__half*)p;
    cudaGetSymbolAddress(&p, g_NodeL);  __half* NodeL  = (__half*)p;
    cudaGetSymbolAddress(&p, g_RelH);   __half* RelH   = (__half*)p;
    cudaGetSymbolAddress(&p, g_RelL);   __half* RelL   = (__half*)p;
    cudaGetSymbolAddress(&p, g_R1H);    __half* R1H    = (__half*)p;
    cudaGetSymbolAddress(&p, g_R1L);    __half* R1L    = (__half*)p;

    static int smem_set = 0;
    if (!smem_set) {
        cudaFuncSetAttribute(gemm_f16<0>, cudaFuncAttributeMaxDynamicSharedMemorySize, GEMM_SMEM_BYTES);
        cudaFuncSetAttribute(gemm_f16<2>, cudaFuncAttributeMaxDynamicSharedMemorySize, GEMM_SMEM_BYTES);
        cudaFuncSetAttribute(gemm_f16<3>, cudaFuncAttributeMaxDynamicSharedMemorySize, GEMM_SMEM_BYTES);
        cudaFuncSetAttribute(gemm_f16<4>, cudaFuncAttributeMaxDynamicSharedMemorySize, GEMM_SMEM_BYTES);
        cudaFuncSetAttribute(gemm_f16<5>, cudaFuncAttributeMaxDynamicSharedMemorySize, GEMM_SMEM_BYTES);
        smem_set = 1;
    }

    const int T = 256;
    // --- merged init ---
    k_init<<<2048, T>>>(out_score, NN, E, NQ);
    // --- merged operand prep (weights + query) ---
    k_prep_all<<<1024, T>>>(W_left, W_right, W_center, W_step, qsrc, qrel, b_left, b_right, NQ);
    // --- merged big splits ---
    k_split_big<<<4096, T>>>(node_rep, rel, NN, E);
    // --- Qc GEMM: bias-folded query term ---
    gemm_f16<2><<<dim3(4, (NQ + 127) / 128), T, GEMM_SMEM_BYTES>>>(
        QinH, QinL, WqH, WqL, Qc, bcat, NQ, 512, 256,
        nullptr, nullptr, nullptr, nullptr, nullptr, nullptr, nullptr, nullptr, nullptr);
    // --- Pnode GEMM ---
    gemm_f16<0><<<dim3(4, (NN + 127) / 128), T, GEMM_SMEM_BYTES>>>(
        NodeH, NodeL, WnodeH, WnodeL, Pnode, nullptr, NN, 512, 128,
        nullptr, nullptr, nullptr, nullptr, nullptr, nullptr, nullptr, nullptr, nullptr);
    // --- Prel GEMM, fused assemble epilogue ---
    gemm_f16<3><<<dim3(4, (E + 127) / 128), T, GEMM_SMEM_BYTES>>>(
        RelH, RelL, WrelH, WrelL, nullptr, nullptr, E, 512, 128,
        idx_i, idx_j, query_idx, Pnode, Qc, Lbuf, R1H, R1L, nullptr);
    // --- center GEMM, fused logits epilogue ---
    gemm_f16<4><<<dim3(2, (E + 127) / 128), T, GEMM_SMEM_BYTES>>>(
        R1H, R1L, WcH, WcL, nullptr, b_center, E, 256, 256,
        nullptr, nullptr, nullptr, nullptr, nullptr, nullptr, nullptr, nullptr, Lbuf);
    // --- segment softmax + score/bucket ---
    k_segmax<<<(E + T - 1) / T, T>>>(idx_i, E);
    k_ex<<<(E + T - 1) / T, T>>>(idx_i, E);
    k_score<<<(E + T - 1) / T, T>>>(idx_i, query_idx, visited, E);
    // --- per-query top-k: one block per query, smem radix select ---
    k_select<<<NQ, 256>>>(max_edges, NQ);
    // --- aggregation into zeroed g_agg ---
    k_aggregate<<<((size_t)E * 32 + T - 1) / T, T>>>(node_rep, idx_i, idx_j, out_score, E);
    // --- step GEMM: A = node_rep + agg, split in-register; bias + leaky ---
    gemm_f16<5><<<dim3(1, (NN + 127) / 128), T, GEMM_SMEM_BYTES>>>(
        nullptr, nullptr, WsH, WsL, out_rep, b_step, NN, 128, 128,
        nullptr, nullptr, nullptr, node_rep, agg, nullptr, nullptr, nullptr, nullptr);
    (void)out_size;
}

// round 17
// speedup vs baseline: 1.1459x; 1.0131x over previous
#include <cuda_runtime.h>
#include <cuda_fp16.h>
#include <cstdint>
#include <math.h>

#define D 128
#define NMAX 100352
#define EMAX 131072
#define NQMAX 128
#define QCAP 4096

// ---------------- static scratch (allocation-free rule) ----------------
__device__ float    g_Qc   [NQMAX * 512];       // query combined (+bias folded)
__device__ float    g_bcat [512];               // [b_left ; b_right]
__device__ float    g_Pnode[NMAX * 512];
__device__ float    g_L  [EMAX * 256];
__device__ float    g_logits[EMAX];
__device__ float    g_ex[EMAX];
__device__ float    g_attn[EMAX];
__device__ float    g_scoreE[EMAX];
__device__ unsigned g_segmax[NMAX];
__device__ float    g_denom[NMAX];
__device__ float    g_agg[NMAX * D];            // attention-weighted message sum (zeroed)
__device__ int      g_keep[EMAX];               // final per-edge keep flag (zeroed)
__device__ int      g_qcnt[NQMAX];              // per-query bucket counts (zeroed)
__device__ unsigned g_qkey [NQMAX * QCAP];      // per-query score keys
__device__ int      g_qedge[NQMAX * QCAP];      // per-query edge ids

// split fp16 operand buffers (hi/lo)
__device__ __align__(128) __half g_WnodeH[512 * 128], g_WnodeL[512 * 128];
__device__ __align__(128) __half g_WrelH [512 * 128], g_WrelL [512 * 128];
__device__ __align__(128) __half g_WqH   [512 * 256], g_WqL   [512 * 256];
__device__ __align__(128) __half g_WcH   [256 * 256], g_WcL   [256 * 256];
__device__ __align__(128) __half g_WsH   [128 * 128], g_WsL   [128 * 128];
__device__ __align__(128) __half g_QinH  [NQMAX * 256], g_QinL[NQMAX * 256];
__device__ __align__(128) __half g_NodeH [NMAX * 128], g_NodeL[NMAX * 128];
__device__ __align__(128) __half g_RelH  [EMAX * 128], g_RelL [EMAX * 128];
__device__ __align__(128) __half g_R1H   [EMAX * 256], g_R1L  [EMAX * 256];

__device__ __forceinline__ float leaky(float x) { return x > 0.f ? x : 0.01f * x; }
__device__ __forceinline__ unsigned f2mono(float f) {
    unsigned b = __float_as_uint(f);
    return (b & 0x80000000u) ? ~b : (b | 0x80000000u);
}
__device__ __forceinline__ float mono2f(unsigned u) {
    return (u & 0x80000000u) ? __uint_as_float(u & 0x7fffffffu) : __uint_as_float(~u);
}
__device__ __forceinline__ uint32_t smem_u32(const void* p) {
    uint32_t a;
    asm("{ .reg .u64 t; cvta.to.shared.u64 t, %1; cvt.u32.u64 %0, t; }" : "=r"(a) : "l"(p));
    return a;
}
__device__ __forceinline__ void split_h(float v, __half& h, __half& l) {
    h = __float2half_rn(v);
    l = __float2half_rn(v - __half2float(h));
}
__device__ __forceinline__ void ldsm4(uint32_t* r, uint32_t addr) {
    asm volatile("ldmatrix.sync.aligned.m8n8.x4.shared.b16 {%0,%1,%2,%3}, [%4];"
                 : "=r"(r[0]), "=r"(r[1]), "=r"(r[2]), "=r"(r[3]) : "r"(addr));
}
__device__ __forceinline__ void mma_f16(float* d, const uint32_t* a, const uint32_t* b) {
    asm volatile(
        "mma.sync.aligned.m16n8k16.row.col.f32.f16.f16.f32 "
        "{%0,%1,%2,%3}, {%4,%5,%6,%7}, {%8,%9}, {%0,%1,%2,%3};"
        : "+f"(d[0]), "+f"(d[1]), "+f"(d[2]), "+f"(d[3])
        : "r"(a[0]), "r"(a[1]), "r"(a[2]), "r"(a[3]), "r"(b[0]), "r"(b[1]));
}

// ================= fp16 3-pass split GEMM: C[M,N] = A[M,K] @ B[N,K]^T =================
// MODE 0: plain store   1: bias+leaky store   2: bias store
// MODE 3: assemble-fused epilogue (Prel GEMM): gathers Pnode/Qc, leaky, writes L + split R1
// MODE 4: logits-fused epilogue (center GEMM): partial dot with L, atomicAdd into g_logits
// MODE 5: A = fp32(Pn + Qc2) summed+split in-register (step GEMM); bias+leaky store
#define ROWH 40
#define TILE_H (128 * ROWH)
#define STAGE_H (4 * TILE_H)
#define GEMM_SMEM_BYTES (2 * STAGE_H * 2)  // 81920 bytes
template <int MODE>
__global__ __launch_bounds__(256) void gemm_f16(const __half* __restrict__ Ah,
                                                const __half* __restrict__ Al,
                                                const __half* __restrict__ Bh,
                                                const __half* __restrict__ Bl,
                                                float* __restrict__ C,
                                                const float* __restrict__ bias,
                                                int M, int N, int K,
                                                const int* __restrict__ idx_i,
                                                const int* __restrict__ idx_j,
                                                const int* __restrict__ qidx,
                                                const float* __restrict__ Pn,
                                                const float* __restrict__ Qc2,
                                                float* __restrict__ outL,
                                                __half* __restrict__ outRH,
                                                __half* __restrict__ outRL,
                                                const float* __restrict__ Lbuf) {
    extern __shared__ __align__(128) __half sm[];
    const int tid = threadIdx.x, lane = tid & 31, wid = tid >> 5;
    const int wm = wid & 1, wn = wid >> 1;
    const int bm = blockIdx.y * 128, bn = blockIdx.x * 128;
    const int rl = lane & 7, q = lane >> 3;

    float acc[4][4][4];
#pragma unroll
    for (int mt = 0; mt < 4; mt++)
#pragma unroll
        for (int nt = 0; nt < 4; nt++)
#pragma unroll
            for (int r = 0; r < 4; r++) acc[mt][nt][r] = 0.f;

    auto load_stage = [&](int st, int kc) {
        if constexpr (MODE == 5) {
#pragma unroll
            for (int i = 0; i < 4; i++) {
                int ch = tid + i * 256;
                int t2 = ch >> 9, r = (ch >> 2) & 127, seg = ch & 3;
                const __half* src = (t2 == 0 ? Bh : Bl) + (size_t)(bn + r) * K + kc + seg * 8;
                uint32_t dst = smem_u32(sm + st * STAGE_H + (2 + t2) * TILE_H + r * ROWH + seg * 8);
                asm volatile("cp.async.cg.shared.global [%0], [%1], 16, 16;"
                             :: "r"(dst), "l"(src));
            }
            asm volatile("cp.async.commit_group;" ::: "memory");
#pragma unroll
            for (int i = 0; i < 4; i++) {
                int s = tid + i * 256;
                int r = s >> 3, c4 = (s & 7) * 4;
                int gm = bm + r;
                float4 va = make_float4(0.f, 0.f, 0.f, 0.f), vb = va;
                if (gm < M) {
                    va = *(const float4*)(Pn + (size_t)gm * K + kc + c4);
                    vb = *(const float4*)(Qc2 + (size_t)gm * K + kc + c4);
                }
                float f0 = va.x + vb.x, f1 = va.y + vb.y, f2 = va.z + vb.z, f3 = va.w + vb.w;
                __half h0, h1, h2, h3, l0, l1, l2, l3;
                split_h(f0, h0, l0); split_h(f1, h1, l1);
                split_h(f2, h2, l2); split_h(f3, h3, l3);
                __half* ah = sm + st * STAGE_H + r * ROWH + c4;
                __half* al = sm + st * STAGE_H + TILE_H + r * ROWH + c4;
                *(__half2*)(ah) = __halves2half2(h0, h1);
                *(__half2*)(ah + 2) = __halves2half2(h2, h3);
                *(__half2*)(al) = __halves2half2(l0, l1);
                *(__half2*)(al + 2) = __halves2half2(l2, l3);
            }
        } else {
#pragma unroll
            for (int i = 0; i < 8; i++) {
                int ch = tid + i * 256;
                int tile = ch >> 9, r = (ch >> 2) & 127, seg = ch & 3;
                const __half* src;
                int sz = 16;
                if (tile < 2) {
                    int row = bm + r;
                    int rc = row < M ? row : 0;
                    sz = row < M ? 16 : 0;
                    src = (tile == 0 ? Ah : Al) + (size_t)rc * K + kc + seg * 8;
                } else {
                    int row = bn + r;
                    src = (tile == 2 ? Bh : Bl) + (size_t)row * K + kc + seg * 8;
                }
                uint32_t dst = smem_u32(sm + st * STAGE_H + tile * TILE_H + r * ROWH + seg * 8);
                asm volatile("cp.async.cg.shared.global [%0], [%1], 16, %2;"
                             :: "r"(dst), "l"(src), "r"(sz));
            }
            asm volatile("cp.async.commit_group;" ::: "memory");
        }
    };

    const int nch = K >> 5;
    load_stage(0, 0);

    for (int c = 0; c < nch; c++) {
        if (c + 1 < nch) {
            load_stage((c + 1) & 1, (c + 1) << 5);
            asm volatile("cp.async.wait_group 1;" ::: "memory");
        } else {
            asm volatile("cp.async.wait_group 0;" ::: "memory");
        }
        __syncthreads();

        const __half* base = sm + (c & 1) * STAGE_H;
        uint32_t aAh = smem_u32(base);
        uint32_t aAl = smem_u32(base + TILE_H);
        uint32_t aBh = smem_u32(base + 2 * TILE_H);
        uint32_t aBl = smem_u32(base + 3 * TILE_H);

#pragma unroll
        for (int ks = 0; ks < 2; ks++) {
            uint32_t ah[4][4], al[4][4], bh[4][2], bl[4][2];
#pragma unroll
            for (int mt = 0; mt < 4; mt++) {
                uint32_t off = ((wm * 64 + mt * 16 + (q & 1) * 8 + rl) * ROWH +
                                ks * 16 + (q >> 1) * 8) * 2;
                ldsm4(ah[mt], aAh + off);
                ldsm4(al[mt], aAl + off);
            }
#pragma unroll
            for (int p = 0; p < 2; p++) {
                uint32_t off = ((wn * 32 + p * 16 + (q >> 1) * 8 + rl) * ROWH +
                                ks * 16 + (q & 1) * 8) * 2;
                uint32_t t[4];
                ldsm4(t, aBh + off);
                bh[2 * p][0] = t[0]; bh[2 * p][1] = t[1];
                bh[2 * p + 1][0] = t[2]; bh[2 * p + 1][1] = t[3];
                ldsm4(t, aBl + off);
                bl[2 * p][0] = t[0]; bl[2 * p][1] = t[1];
                bl[2 * p + 1][0] = t[2]; bl[2 * p + 1][1] = t[3];
            }
#pragma unroll
            for (int mt = 0; mt < 4; mt++)
#pragma unroll
                for (int nt = 0; nt < 4; nt++) {
                    mma_f16(acc[mt][nt], ah[mt], bh[nt]);
                    mma_f16(acc[mt][nt], ah[mt], bl[nt]);
                    mma_f16(acc[mt][nt], al[mt], bh[nt]);
                }
        }
        __syncthreads();
    }

    // ---- epilogues ----
    const int g = lane >> 2, t4 = lane & 3;

    if constexpr (MODE == 3) {
        int* si = (int*)sm;
        if (tid < 128) {
            int e = bm + tid;
            si[tid] = idx_i[e];
            si[128 + tid] = idx_j[e];
            si[256 + tid] = qidx[e];
        }
        __syncthreads();
#pragma unroll
        for (int mt = 0; mt < 4; mt++) {
            int rl0 = wm * 64 + mt * 16 + g;
            int i0 = si[rl0], j0 = si[128 + rl0], q0 = si[256 + rl0];
            int i1 = si[rl0 + 8], j1 = si[128 + rl0 + 8], q1 = si[256 + rl0 + 8];
            size_t e0 = (size_t)bm + rl0, e1 = e0 + 8;
#pragma unroll
            for (int nt = 0; nt < 4; nt++) {
                int col = bn + wn * 32 + nt * 8 + t4 * 2;
                bool left = col < 256;
                int b0 = left ? i0 : j0, b1 = left ? i1 : j1;
                float2 pn0 = *(const float2*)(Pn + (size_t)b0 * 512 + col);
                float2 qc0 = *(const float2*)(Qc2 + (size_t)q0 * 512 + col);
                float2 pn1 = *(const float2*)(Pn + (size_t)b1 * 512 + col);
                float2 qc1 = *(const float2*)(Qc2 + (size_t)q1 * 512 + col);
                float v0 = leaky(acc[mt][nt][0] + pn0.x + qc0.x);
                float v1 = leaky(acc[mt][nt][1] + pn0.y + qc0.y);
                float v2 = leaky(acc[mt][nt][2] + pn1.x + qc1.x);
                float v3 = leaky(acc[mt][nt][3] + pn1.y + qc1.y);
                if (left) {
                    *(float2*)(outL + e0 * 256 + col) = make_float2(v0, v1);
                    *(float2*)(outL + e1 * 256 + col) = make_float2(v2, v3);
                } else {
                    __half h0, l0, h1, l1, h2, l2, h3, l3;
                    split_h(v0, h0, l0); split_h(v1, h1, l1);
                    split_h(v2, h2, l2); split_h(v3, h3, l3);
                    size_t o0 = e0 * 256 + col - 256, o1 = e1 * 256 + col - 256;
                    *(__half2*)(outRH + o0) = __halves2half2(h0, h1);
                    *(__half2*)(outRL + o0) = __halves2half2(l0, l1);
                    *(__half2*)(outRH + o1) = __halves2half2(h2, h3);
                    *(__half2*)(outRL + o1) = __halves2half2(l2, l3);
                }
            }
        }
    } else if constexpr (MODE == 4) {
#pragma unroll
        for (int mt = 0; mt < 4; mt++) {
            int r0 = bm + wm * 64 + mt * 16 + g;
            float p0 = 0.f, p1 = 0.f;
#pragma unroll
            for (int nt = 0; nt < 4; nt++) {
                int col = bn + wn * 32 + nt * 8 + t4 * 2;
                float b0 = bias[col], b1 = bias[col + 1];
                float2 l0 = *(const float2*)(Lbuf + (size_t)r0 * 256 + col);
                float2 l1 = *(const float2*)(Lbuf + (size_t)(r0 + 8) * 256 + col);
                p0 = fmaf(l0.x, acc[mt][nt][0] + b0, p0);
                p0 = fmaf(l0.y, acc[mt][nt][1] + b1, p0);
                p1 = fmaf(l1.x, acc[mt][nt][2] + b0, p1);
                p1 = fmaf(l1.y, acc[mt][nt][3] + b1, p1);
            }
            p0 += __shfl_xor_sync(0xffffffffu, p0, 1);
            p0 += __shfl_xor_sync(0xffffffffu, p0, 2);
            p1 += __shfl_xor_sync(0xffffffffu, p1, 1);
            p1 += __shfl_xor_sync(0xffffffffu, p1, 2);
            if (t4 == 0) {
                atomicAdd(&g_logits[r0], p0);
                atomicAdd(&g_logits[r0 + 8], p1);
            }
        }
    } else {
#pragma unroll
        for (int mt = 0; mt < 4; mt++) {
            int row0 = bm + wm * 64 + mt * 16 + g;
#pragma unroll
            for (int nt = 0; nt < 4; nt++) {
                int col = bn + wn * 32 + nt * 8 + t4 * 2;
                float d0 = acc[mt][nt][0], d1 = acc[mt][nt][1];
                float d2 = acc[mt][nt][2], d3 = acc[mt][nt][3];
                if (MODE == 1 || MODE == 2 || MODE == 5) {
                    float b0 = bias[col], b1 = bias[col + 1];
                    d0 += b0; d1 += b1; d2 += b0; d3 += b1;
                    if (MODE == 1 || MODE == 5) {
                        d0 = leaky(d0); d1 = leaky(d1);
                        d2 = leaky(d2); d3 = leaky(d3);
                    }
                }
                if (row0 < M) *(float2*)(C + (size_t)row0 * N + col) = make_float2(d0, d1);
                if (row0 + 8 < M) *(float2*)(C + (size_t)(row0 + 8) * N + col) = make_float2(d2, d3);
            }
        }
    }
}

// ---------------- merged init: zero all state in one launch ----------------
__global__ void k_init(float* __restrict__ out_score, int NN, int E, int NQ) {
    int gs = gridDim.x * blockDim.x;
    int gtid = blockIdx.x * blockDim.x + threadIdx.x;
    for (int t = gtid; t < NN * D; t += gs) g_agg[t] = 0.f;
    for (int t = gtid; t < NN; t += gs) {
        g_segmax[t] = 0u;
        g_denom[t] = 0.f;
        out_score[t] = 0.f;
    }
    for (int t = gtid; t < E; t += gs) {
        g_keep[t] = 0;
        g_logits[t] = 0.f;
    }
    for (int t = gtid; t < NQ; t += gs) g_qcnt[t] = 0;
}

// ---------------- merged operand prep (weights + query) ----------------
__global__ void k_prep_all(const float* __restrict__ Wl, const float* __restrict__ Wr,
                           const float* __restrict__ Wc, const float* __restrict__ Ws,
                           const float* __restrict__ qs, const float* __restrict__ qr,
                           const float* __restrict__ bl, const float* __restrict__ br,
                           int NQ) {
    int gs = gridDim.x * blockDim.x;
    int gtid = blockIdx.x * blockDim.x + threadIdx.x;
    __half h, l;
    // W_left / W_right repack+split
    for (int t = gtid; t < 512 * 512; t += gs) {
        int j = t >> 9, k = t & 511;
        float v = (j < 256) ? Wl[(size_t)j * 512 + k] : Wr[(size_t)(j - 256) * 512 + k];
        split_h(v, h, l);
        if (k < 128)      { g_WnodeH[j * 128 + k] = h;       g_WnodeL[j * 128 + k] = l; }
        else if (k < 256) { g_WrelH[j * 128 + k - 128] = h;  g_WrelL[j * 128 + k - 128] = l; }
        else              { g_WqH[j * 256 + k - 256] = h;    g_WqL[j * 256 + k - 256] = l; }
    }
    // W_center split
    for (int t = gtid; t < 256 * 256; t += gs) {
        split_h(Wc[t], h, l);
        g_WcH[t] = h; g_WcL[t] = l;
    }
    // W_step split
    for (int t = gtid; t < 128 * 128; t += gs) {
        split_h(Ws[t], h, l);
        g_WsH[t] = h; g_WsL[t] = l;
    }
    // query concat + split
    for (int t = gtid; t < NQ * 256; t += gs) {
        int q = t >> 8, k = t & 255;
        float v = (k < 128) ? qs[q * 128 + k] : qr[q * 128 + (k - 128)];
        split_h(v, h, l);
        g_QinH[t] = h; g_QinL[t] = l;
    }
    if (gtid < 512) g_bcat[gtid] = (gtid < 256) ? bl[gtid] : br[gtid - 256];
}

// ---------------- merged big splits (node_rep + rel) ----------------
__global__ void k_split_big(const float* __restrict__ node_rep, const float* __restrict__ rel,
                            int NN, int E) {
    int gs = gridDim.x * blockDim.x;
    int gtid = blockIdx.x * blockDim.x + threadIdx.x;
    int n4a = NN * 32;  // NN*128/4
    int n4b = E * 32;
    __half h0, h1, h2, h3, l0, l1, l2, l3;
    for (int i = gtid; i < n4a; i += gs) {
        float4 v = ((const float4*)node_rep)[i];
        split_h(v.x, h0, l0); split_h(v.y, h1, l1);
        split_h(v.z, h2, l2); split_h(v.w, h3, l3);
        ((__half2*)g_NodeH)[i * 2 + 0] = __halves2half2(h0, h1);
        ((__half2*)g_NodeH)[i * 2 + 1] = __halves2half2(h2, h3);
        ((__half2*)g_NodeL)[i * 2 + 0] = __halves2half2(l0, l1);
        ((__half2*)g_NodeL)[i * 2 + 1] = __halves2half2(l2, l3);
    }
    for (int i = gtid; i < n4b; i += gs) {
        float4 v = ((const float4*)rel)[i];
        split_h(v.x, h0, l0); split_h(v.y, h1, l1);
        split_h(v.z, h2, l2); split_h(v.w, h3, l3);
        ((__half2*)g_RelH)[i * 2 + 0] = __halves2half2(h0, h1);
        ((__half2*)g_RelH)[i * 2 + 1] = __halves2half2(h2, h3);
        ((__half2*)g_RelL)[i * 2 + 0] = __halves2half2(l0, l1);
        ((__half2*)g_RelL)[i * 2 + 1] = __halves2half2(l2, l3);
    }
}

// segment max over logits
__global__ void k_segmax(const int* __restrict__ idx_i, int E) {
    int e = blockIdx.x * blockDim.x + threadIdx.x;
    if (e >= E) return;
    atomicMax(&g_segmax[idx_i[e]], f2mono(g_logits[e]));
}
__global__ void k_ex(const int* __restrict__ idx_i, int E) {
    int e = blockIdx.x * blockDim.x + threadIdx.x;
    if (e >= E) return;
    int i = idx_i[e];
    float m = mono2f(g_segmax[i]);
    float ex = expf(g_logits[e] - m);
    g_ex[e] = ex;
    atomicAdd(&g_denom[i], ex);
}
// score + per-query bucket append
__global__ void k_score(const int* __restrict__ idx_i, const int* __restrict__ qidx,
                        const float* __restrict__ visited, int E) {
    int e = blockIdx.x * blockDim.x + threadIdx.x;
    if (e >= E) return;
    int i = idx_i[e];
    float a = g_ex[e] / g_denom[i];
    g_attn[e] = a;
    float sc = a * visited[i];
    g_scoreE[e] = sc;
    int q = qidx[e];
    int p = atomicAdd(&g_qcnt[q], 1);
    if (p < QCAP) {
        g_qkey[q * QCAP + p] = __float_as_uint(sc);   // sc >= 0 -> bits monotonic
        g_qedge[q * QCAP + p] = e;
    }
}

// ---------------- per-query top-k: one block per query, smem radix select ----------------
__global__ __launch_bounds__(256) void k_select(const int* __restrict__ max_edges, int NQ) {
    __shared__ unsigned hist[256];
    __shared__ unsigned sprefix;
    __shared__ int skr;
    __shared__ int eqn;
    __shared__ int eqedge[1024];
    int q = blockIdx.x;
    if (q >= NQ) return;
    int n = min(g_qcnt[q], QCAP);
    int k = max_edges ? *max_edges : 1024;
    const unsigned* keys = g_qkey + (size_t)q * QCAP;
    const int* edges = g_qedge + (size_t)q * QCAP;

    if (n <= k) {            // whole group kept
        for (int t = threadIdx.x; t < n; t += 256) g_keep[edges[t]] = 1;
        return;
    }
    if (threadIdx.x == 0) { sprefix = 0u; skr = k; eqn = 0; }
    __syncthreads();
#pragma unroll
    for (int pass = 0; pass < 4; pass++) {
        int shift = 24 - pass * 8;
        hist[threadIdx.x] = 0u;
        __syncthreads();
        unsigned pref = sprefix;
        for (int t = threadIdx.x; t < n; t += 256) {
            unsigned u = keys[t];
            if (pass == 0 || (u >> (shift + 8)) == (pref >> (shift + 8)))
                atomicAdd(&hist[(u >> shift) & 255u], 1u);
        }
        __syncthreads();
        if (threadIdx.x == 0) {
            unsigned kr = (unsigned)skr, c = 0;
            for (int b = 255; b >= 0; b--) {
                unsigned h = hist[b];
                if (c + h >= kr) {
                    sprefix = pref | (((unsigned)b) << shift);
                    skr = (int)(kr - c);
                    break;
                }
                c += h;
            }
        }
        __syncthreads();
    }
    unsigned T = sprefix;
    int kr = skr;
    // keep strictly-greater; collect equals
    for (int t = threadIdx.x; t < n; t += 256) {
        unsigned u = keys[t];
        if (u > T) g_keep[edges[t]] = 1;
        else if (u == T) {
            int p = atomicAdd(&eqn, 1);
            if (p < 1024) eqedge[p] = edges[t];
        }
    }
    __syncthreads();
    int m = min(eqn, 1024);
    // stable tiebreak among equals: smallest original edge id wins
    for (int t = threadIdx.x; t < m; t += 256) {
        int me = eqedge[t];
        int cnt = 0;
        for (int jj = 0; jj < m; jj++) cnt += (eqedge[jj] < me);
        if (cnt < kr) g_keep[me] = 1;
    }
}

// ---------------- pruned aggregation (into zeroed g_agg) ----------------
__global__ void k_aggregate(const float* __restrict__ node_rep,
                            const int* __restrict__ idx_i, const int* __restrict__ idx_j,
                            float* __restrict__ out_score, int E) {
    int w = (blockIdx.x * blockDim.x + threadIdx.x) >> 5;
    int lane = threadIdx.x & 31;
    if (w >= E) return;
    if (!g_keep[w]) return;
    int i = idx_i[w], j = idx_j[w];
    if (lane == 0) atomicAdd(out_score + j, g_scoreE[w]);
    float a = g_attn[w];
    float4 h = *(const float4*)(node_rep + (size_t)i * D + lane * 4);
#if __CUDA_ARCH__ >= 900
    atomicAdd((float4*)(g_agg + (size_t)j * D + lane * 4),
              make_float4(a * h.x, a * h.y, a * h.z, a * h.w));
#else
    float* dst = g_agg + (size_t)j * D + lane * 4;
    atomicAdd(dst + 0, a * h.x);
    atomicAdd(dst + 1, a * h.y);
    atomicAdd(dst + 2, a * h.z);
    atomicAdd(dst + 3, a * h.w);
#endif
}

// ---------------- launch ----------------
extern "C" void kernel_launch(void* const* d_in, const int* in_sizes, int n_in,
                              void* d_out, int out_size) {
    const float* visited  = (const float*)d_in[0];
    const float* node_rep = (const float*)d_in[1];
    const float* qsrc     = (const float*)d_in[2];
    const float* qrel     = (const float*)d_in[3];
    const float* rel      = (const float*)d_in[4];
    const float* W_left   = (const float*)d_in[5];
    const float* b_left   = (const float*)d_in[6];
    const float* W_right  = (const float*)d_in[7];
    const float* b_right  = (const float*)d_in[8];
    const float* W_center = (const float*)d_in[9];
    const float* b_center = (const float*)d_in[10];
    const float* W_step   = (const float*)d_in[11];
    const float* b_step   = (const float*)d_in[12];
    const int* query_idx  = (const int*)d_in[13];
    const int* idx_i      = (const int*)d_in[14];
    const int* idx_j      = (const int*)d_in[15];
    const int* max_edges  = (n_in >= 17) ? (const int*)d_in[16] : nullptr;

    int NN = in_sizes[0];
    int E  = in_sizes[13];
    int NQ = in_sizes[2] / D;

    float* out_score = (float*)d_out;
    float* out_rep   = (float*)d_out + NN;

    void* p;
    cudaGetSymbolAddress(&p, g_Pnode);  float* Pnode  = (float*)p;
    cudaGetSymbolAddress(&p, g_Qc);     float* Qc     = (float*)p;
    cudaGetSymbolAddress(&p, g_bcat);   float* bcat   = (float*)p;
    cudaGetSymbolAddress(&p, g_L);      float* Lbuf   = (float*)p;
    cudaGetSymbolAddress(&p, g_agg);    float* agg    = (float*)p;
    cudaGetSymbolAddress(&p, g_WnodeH); __half* WnodeH = (__half*)p;
    cudaGetSymbolAddress(&p, g_WnodeL); __half* WnodeL = (__half*)p;
    cudaGetSymbolAddress(&p, g_WrelH);  __half* WrelH  = (__half*)p;
    cudaGetSymbolAddress(&p, g_WrelL);  __half* WrelL  = (__half*)p;
    cudaGetSymbolAddress(&p, g_WqH);    __half* WqH    = (__half*)p;
    cudaGetSymbolAddress(&p, g_WqL);    __half* WqL    = (__half*)p;
    cudaGetSymbolAddress(&p, g_WcH);    __half* WcH    = (__half*)p;
    cudaGetSymbolAddress(&p, g_WcL);    __half* WcL    = (__half*)p;
    cudaGetSymbolAddress(&p, g_WsH);    __half* WsH    = (__half*)p;
    cudaGetSymbolAddress(&p, g_WsL);    __half* WsL    = (__half*)p;
    cudaGetSymbolAddress(&p, g_QinH);   __half* QinH   = (__half*)p;
    cudaGetSymbolAddress(&p, g_QinL);   __half* QinL   = (__half*)p;
    cudaGetSymbolAddress(&p, g_NodeH);  __half* NodeH  = (__half*)p;
    cudaGetSymbolAddress(&p, g_NodeL);  __half* NodeL  = (__half*)p;
    cudaGetSymbolAddress(&p, g_RelH);   __half* RelH   = (__half*)p;
    cudaGetSymbolAddress(&p, g_RelL);   __half* RelL   = (__half*)p;
    cudaGetSymbolAddress(&p, g_R1H);    __half* R1H    = (__half*)p;
    cudaGetSymbolAddress(&p, g_R1L);    __half* R1L    = (__half*)p;

    static int inited = 0;
    static cudaStream_t s1;
    static cudaEvent_t evRoot, evPrep, evQc;
    if (!inited) {
        cudaFuncSetAttribute(gemm_f16<0>, cudaFuncAttributeMaxDynamicSharedMemorySize, GEMM_SMEM_BYTES);
        cudaFuncSetAttribute(gemm_f16<2>, cudaFuncAttributeMaxDynamicSharedMemorySize, GEMM_SMEM_BYTES);
        cudaFuncSetAttribute(gemm_f16<3>, cudaFuncAttributeMaxDynamicSharedMemorySize, GEMM_SMEM_BYTES);
        cudaFuncSetAttribute(gemm_f16<4>, cudaFuncAttributeMaxDynamicSharedMemorySize, GEMM_SMEM_BYTES);
        cudaFuncSetAttribute(gemm_f16<5>, cudaFuncAttributeMaxDynamicSharedMemorySize, GEMM_SMEM_BYTES);
        cudaStreamCreateWithFlags(&s1, cudaStreamNonBlocking);
        cudaEventCreateWithFlags(&evRoot, cudaEventDisableTiming);
        cudaEventCreateWithFlags(&evPrep, cudaEventDisableTiming);
        cudaEventCreateWithFlags(&evQc, cudaEventDisableTiming);
        inited = 1;
    }

    const int T = 256;
    // --- fork: weight/query prep + Qc GEMM on side stream ---
    cudaEventRecord(evRoot, 0);
    cudaStreamWaitEvent(s1, evRoot, 0);
    k_prep_all<<<1024, T, 0, s1>>>(W_left, W_right, W_center, W_step, qsrc, qrel, b_left, b_right, NQ);
    cudaEventRecord(evPrep, s1);
    gemm_f16<2><<<dim3(4, (NQ + 127) / 128), T, GEMM_SMEM_BYTES, s1>>>(
        QinH, QinL, WqH, WqL, Qc, bcat, NQ, 512, 256,
        nullptr, nullptr, nullptr, nullptr, nullptr, nullptr, nullptr, nullptr, nullptr);
    cudaEventRecord(evQc, s1);
    // --- main stream: init + big splits (overlap with side stream) ---
    k_init<<<2048, T>>>(out_score, NN, E, NQ);
    k_split_big<<<4096, T>>>(node_rep, rel, NN, E);
    // --- Pnode GEMM (needs split + prep) ---
    cudaStreamWaitEvent(0, evPrep, 0);
    gemm_f16<0><<<dim3(4, (NN + 127) / 128), T, GEMM_SMEM_BYTES>>>(
        NodeH, NodeL, WnodeH, WnodeL, Pnode, nullptr, NN, 512, 128,
        nullptr, nullptr, nullptr, nullptr, nullptr, nullptr, nullptr, nullptr, nullptr);
    // --- Prel GEMM, fused assemble epilogue (needs Pnode + Qc) ---
    cudaStreamWaitEvent(0, evQc, 0);
    gemm_f16<3><<<dim3(4, (E + 127) / 128), T, GEMM_SMEM_BYTES>>>(
        RelH, RelL, WrelH, WrelL, nullptr, nullptr, E, 512, 128,
        idx_i, idx_j, query_idx, Pnode, Qc, Lbuf, R1H, R1L, nullptr);
    // --- center GEMM, fused logits epilogue ---
    gemm_f16<4><<<dim3(2, (E + 127) / 128), T, GEMM_SMEM_BYTES>>>(
        R1H, R1L, WcH, WcL, nullptr, b_center, E, 256, 256,
        nullptr, nullptr, nullptr, nullptr, nullptr, nullptr, nullptr, nullptr, Lbuf);
    // --- segment softmax + score/bucket ---
    k_segmax<<<(E + T - 1) / T, T>>>(idx_i, E);
    k_ex<<<(E + T - 1) / T, T>>>(idx_i, E);
    k_score<<<(E + T - 1) / T, T>>>(idx_i, query_idx, visited, E);
    // --- per-query top-k: one block per query, smem radix select ---
    k_select<<<NQ, 256>>>(max_edges, NQ);
    // --- aggregation into zeroed g_agg ---
    k_aggregate<<<((size_t)E * 32 + T - 1) / T, T>>>(node_rep, idx_i, idx_j, out_score, E);
    // --- step GEMM: A = node_rep + agg, split in-register; bias + leaky ---
    gemm_f16<5><<<dim3(1, (NN + 127) / 128), T, GEMM_SMEM_BYTES>>>(
        nullptr, nullptr, WsH, WsL, out_rep, b_step, NN, 128, 128,
        nullptr, nullptr, nullptr, node_rep, agg, nullptr, nullptr, nullptr, nullptr);
    (void)out_size;
}